// round 15
// baseline (speedup 1.0000x reference)
#include <cuda_runtime.h>
#include <cuda_bf16.h>
#include <math.h>
#include <stdint.h>

#define NB 4
#define NS 256
#define NNODE 500
#define DH 64
#define G3 192

typedef unsigned long long u64;

// ---------------- device scratch (no allocations allowed) ----------------
__device__ float g_x[(size_t)NB * NS * NNODE * DH];   // 131 MB activations, in-place across layers
__device__ float g_adjT[NNODE * NNODE];               // adjT[m][n] = adj[n][m] fp32
__device__ __nv_bfloat16 g_adjT_h[512 * 512];         // bf16 split hi, zero-padded to 512x512
__device__ __nv_bfloat16 g_adjT_l[512 * 512];         // bf16 split lo
__device__ float g_part[2148864];                     // split-K partials: l @0, m @1572864, s @1956864
__device__ float g_xp_l[1024 * G3];
__device__ float g_xp_m[80 * G3];
__device__ float g_xp_s[40 * G3];
__device__ float g_hfin[3 * NB * DH];                 // [s,m,l][b][j]

__device__ __forceinline__ float geluf(float x) { return 0.5f * x * (1.0f + erff(x * 0.7071067811865476f)); }
__device__ __forceinline__ float sigf(float x)  { return 1.0f / (1.0f + expf(-x)); }

// packed fp32x2 helpers (exact fp32 math)
__device__ __forceinline__ u64 splat2(float a) {
    u64 r; asm("mov.b64 %0, {%1, %1};" : "=l"(r) : "f"(a)); return r;
}
__device__ __forceinline__ u64 ffma2(u64 a, u64 b, u64 c) {
    u64 d; asm("fma.rn.f32x2 %0, %1, %2, %3;" : "=l"(d) : "l"(a), "l"(b), "l"(c)); return d;
}
__device__ __forceinline__ float2 unpack2(u64 v) {
    float2 f; asm("mov.b64 {%0, %1}, %2;" : "=f"(f.x), "=f"(f.y) : "l"(v)); return f;
}

// HMMA m16n8k16 bf16, fp32 accum (base-target instruction, runs on tensor pipe)
__device__ __forceinline__ void mma16816(float* c, const uint32_t* a, const uint32_t* b) {
    asm volatile("mma.sync.aligned.m16n8k16.row.col.f32.bf16.bf16.f32 "
        "{%0,%1,%2,%3}, {%4,%5,%6,%7}, {%8,%9}, {%0,%1,%2,%3};"
        : "+f"(c[0]), "+f"(c[1]), "+f"(c[2]), "+f"(c[3])
        : "r"(a[0]), "r"(a[1]), "r"(a[2]), "r"(a[3]), "r"(b[0]), "r"(b[1]));
}

// ---------------- adjacency: logits + row softmax, stored transposed ----------------
__global__ void k_adj(const float* __restrict__ fe, const float* __restrict__ tem) {
    __shared__ float sf[32];
    __shared__ float lg[NNODE];
    __shared__ float wred[8];
    int n = blockIdx.x, tid = threadIdx.x;
    if (tid < 32) sf[tid] = fe[n * 32 + tid];
    __syncthreads();
    for (int m = tid; m < NNODE; m += 256) {
        float a = 0.f;
        #pragma unroll
        for (int k = 0; k < 32; k++) a += sf[k] * tem[m * 32 + k];
        lg[m] = a * 2.0f;   // / TEMP (0.5)
    }
    __syncthreads();
    float mx = -1e30f;
    for (int m = tid; m < NNODE; m += 256) mx = fmaxf(mx, lg[m]);
    for (int o = 16; o; o >>= 1) mx = fmaxf(mx, __shfl_xor_sync(0xffffffffu, mx, o));
    if ((tid & 31) == 0) wred[tid >> 5] = mx;
    __syncthreads();
    mx = wred[0];
    #pragma unroll
    for (int w = 1; w < 8; w++) mx = fmaxf(mx, wred[w]);
    float sum = 0.f;
    for (int m = tid; m < NNODE; m += 256) { float e = expf(lg[m] - mx); lg[m] = e; sum += e; }
    for (int o = 16; o; o >>= 1) sum += __shfl_xor_sync(0xffffffffu, sum, o);
    __syncthreads();
    if ((tid & 31) == 0) wred[tid >> 5] = sum;
    __syncthreads();
    sum = 0.f;
    #pragma unroll
    for (int w = 0; w < 8; w++) sum += wred[w];
    float inv = 1.0f / sum;
    for (int m = tid; m < NNODE; m += 256) g_adjT[m * NNODE + n] = lg[m] * inv;
}

// ---------------- adjT bf16 split, zero-padded 512x512 ----------------
__global__ void k_adjsplit() {
    int m = blockIdx.x;
    for (int k = threadIdx.x; k < 512; k += 256) {
        float v = (m < NNODE && k < NNODE) ? g_adjT[m * NNODE + k] : 0.f;
        __nv_bfloat16 h16 = __float2bfloat16(v);
        __nv_bfloat16 l16 = __float2bfloat16(v - __bfloat162float(h16));
        g_adjT_h[m * 512 + k] = h16;
        g_adjT_l[m * 512 + k] = l16;
    }
}

// ---------------- input projection: 64 rows/block, W loaded once ----------------
__global__ __launch_bounds__(512) void k_iproj(const float* __restrict__ x,
                                               const float* __restrict__ W,
                                               const float* __restrict__ b) {
    __shared__ float sW[64 * 33];
    __shared__ float sb[64];
    __shared__ float sx[64 * 32];
    int tid = threadIdx.x;
    for (int i = tid; i < 2048; i += 512) { int d = i >> 5, k = i & 31; sW[d * 33 + k] = W[i]; }
    if (tid < 64) sb[tid] = b[tid];
    size_t row0 = (size_t)blockIdx.x * 64;
    for (int i = tid; i < 2048; i += 512) sx[i] = x[row0 * 32 + i];
    __syncthreads();
    int r = tid >> 6, d = tid & 63;
    #pragma unroll
    for (int g = 0; g < 8; g++) {
        int rr = g * 8 + r;
        float a = sb[d];
        #pragma unroll
        for (int k = 0; k < 32; k++) a += sx[rr * 32 + k] * sW[d * 33 + k];
        g_x[(row0 + rr) * 64 + d] = geluf(a);
    }
}

// ---------------- fused graph layer: HMMA bf16-split agg (N-split, spill-free) + fp32 mm2/gelu/LN ----------------
// phase1 smem: xsTh [64][520]bf16 @0 (66560) | xsTl @66560 (66560) -> 133120
// persistent:  Ws @133120 (17408) -> 150528 | params @150528 (1792) -> 152320
// phase2 overlays dead xsT region: xas [128][68] @0 (34816) | hstage [128][68] @36864 (-> 71680)
#define XSTR 520
#define LAYER_SMEM_BYTES 152320
__global__ __launch_bounds__(512) void k_layer(const float* __restrict__ W,
                                               const float* __restrict__ bias2,
                                               const float* __restrict__ gamma,
                                               const float* __restrict__ beta) {
    extern __shared__ __align__(16) char smb[];
    __nv_bfloat16* xsTh = (__nv_bfloat16*)smb;            // [64][520]
    __nv_bfloat16* xsTl = (__nv_bfloat16*)(smb + 66560);  // [64][520]
    float* xas    = (float*)smb;                          // phase2 [128][68]
    float* hstage = (float*)(smb + 36864);                // phase2 [128][68]
    float* Ws     = (float*)(smb + 133120);               // [64][68]
    float* b2S    = (float*)(smb + 150528);
    float* gS  = b2S + 64;
    float* beS = gS + 64;
    float* muS = beS + 64;                                // [128]
    float* rsS = muS + 128;                               // [128]
    int tid = threadIdx.x, wid = tid >> 5, lid = tid & 31;
    float* gx = g_x + (size_t)blockIdx.x * (NNODE * DH);

    // weights / LN params
    for (int i = tid; i < 4096; i += 512) { int e = i >> 6, d = i & 63; Ws[e * 68 + d] = W[i]; }
    if (tid < 64) { b2S[tid] = bias2[tid]; gS[tid] = gamma[tid]; beS[tid] = beta[tid]; }

    // build xs^T bf16 hi/lo: xsT[n][k], k zero-padded beyond NNODE
    for (int idx = tid; idx < 32768; idx += 512) {
        int n = idx & 63, k = idx >> 6;
        float v = (k < NNODE) ? gx[(size_t)k * 64 + n] : 0.f;
        __nv_bfloat16 h16 = __float2bfloat16(v);
        __nv_bfloat16 l16 = __float2bfloat16(v - __bfloat162float(h16));
        xsTh[n * XSTR + k] = h16;
        xsTl[n * XSTR + k] = l16;
    }
    __syncthreads();

    // ---- agg via HMMA: warp w rows [w*32, w*32+32); two N-halves of 32 cols (acc 32 regs) ----
    int gr = lid >> 2;            // 0..7
    int kc = (lid & 3) << 1;      // 0,2,4,6
    int m0 = wid * 32;
    int ra = m0 + gr, rb = m0 + 16 + gr;

    for (int half = 0; half < 2; half++) {
        float acc[8][4];          // tile t = mt*4+nt (mt 0..1, nt 0..3)
        #pragma unroll
        for (int t = 0; t < 8; t++)
            #pragma unroll
            for (int q = 0; q < 4; q++) acc[t][q] = 0.f;

        #pragma unroll 2
        for (int ks = 0; ks < 32; ks++) {
            int k0 = ks * 16 + kc;
            uint32_t ah[8], aw[8], bb[8];
            ah[0] = *(const uint32_t*)(g_adjT_h + (size_t)ra * 512 + k0);
            ah[1] = *(const uint32_t*)(g_adjT_h + (size_t)(ra + 8) * 512 + k0);
            ah[2] = *(const uint32_t*)(g_adjT_h + (size_t)ra * 512 + k0 + 8);
            ah[3] = *(const uint32_t*)(g_adjT_h + (size_t)(ra + 8) * 512 + k0 + 8);
            ah[4] = *(const uint32_t*)(g_adjT_h + (size_t)rb * 512 + k0);
            ah[5] = *(const uint32_t*)(g_adjT_h + (size_t)(rb + 8) * 512 + k0);
            ah[6] = *(const uint32_t*)(g_adjT_h + (size_t)rb * 512 + k0 + 8);
            ah[7] = *(const uint32_t*)(g_adjT_h + (size_t)(rb + 8) * 512 + k0 + 8);
            #pragma unroll
            for (int nt = 0; nt < 4; nt++) {
                int ntg = half * 4 + nt;
                bb[nt * 2]     = *(const uint32_t*)&xsTh[(ntg * 8 + gr) * XSTR + k0];
                bb[nt * 2 + 1] = *(const uint32_t*)&xsTh[(ntg * 8 + gr) * XSTR + k0 + 8];
            }
            #pragma unroll
            for (int mt = 0; mt < 2; mt++)
                #pragma unroll
                for (int nt = 0; nt < 4; nt++)
                    mma16816(acc[mt * 4 + nt], &ah[mt * 4], &bb[nt * 2]);   // hi*hi
            aw[0] = *(const uint32_t*)(g_adjT_l + (size_t)ra * 512 + k0);
            aw[1] = *(const uint32_t*)(g_adjT_l + (size_t)(ra + 8) * 512 + k0);
            aw[2] = *(const uint32_t*)(g_adjT_l + (size_t)ra * 512 + k0 + 8);
            aw[3] = *(const uint32_t*)(g_adjT_l + (size_t)(ra + 8) * 512 + k0 + 8);
            aw[4] = *(const uint32_t*)(g_adjT_l + (size_t)rb * 512 + k0);
            aw[5] = *(const uint32_t*)(g_adjT_l + (size_t)(rb + 8) * 512 + k0);
            aw[6] = *(const uint32_t*)(g_adjT_l + (size_t)rb * 512 + k0 + 8);
            aw[7] = *(const uint32_t*)(g_adjT_l + (size_t)(rb + 8) * 512 + k0 + 8);
            #pragma unroll
            for (int mt = 0; mt < 2; mt++)
                #pragma unroll
                for (int nt = 0; nt < 4; nt++)
                    mma16816(acc[mt * 4 + nt], &aw[mt * 4], &bb[nt * 2]);   // lo*hi
            #pragma unroll
            for (int nt = 0; nt < 4; nt++) {
                int ntg = half * 4 + nt;
                bb[nt * 2]     = *(const uint32_t*)&xsTl[(ntg * 8 + gr) * XSTR + k0];
                bb[nt * 2 + 1] = *(const uint32_t*)&xsTl[(ntg * 8 + gr) * XSTR + k0 + 8];
            }
            #pragma unroll
            for (int mt = 0; mt < 2; mt++)
                #pragma unroll
                for (int nt = 0; nt < 4; nt++)
                    mma16816(acc[mt * 4 + nt], &ah[mt * 4], &bb[nt * 2]);   // hi*lo
        }
        // epilogue this half: xa = x + agg, written back into gx (each warp owns its rows/cols)
        #pragma unroll
        for (int mt = 0; mt < 2; mt++) {
            #pragma unroll
            for (int nt = 0; nt < 4; nt++) {
                float* a4 = acc[mt * 4 + nt];
                int r1 = m0 + mt * 16 + gr;
                int r2 = r1 + 8;
                int c  = half * 32 + nt * 8 + kc;
                if (r1 < NNODE) {
                    float2 res = *(const float2*)(gx + (size_t)r1 * 64 + c);
                    *(float2*)(gx + (size_t)r1 * 64 + c) = make_float2(res.x + a4[0], res.y + a4[1]);
                }
                if (r2 < NNODE) {
                    float2 res = *(const float2*)(gx + (size_t)r2 * 64 + c);
                    *(float2*)(gx + (size_t)r2 * 64 + c) = make_float2(res.x + a4[2], res.y + a4[3]);
                }
            }
        }
    }
    __syncthreads();   // all xa writes to gx visible; xsT dead

    // ---- mm2 + gelu + layernorm in 4 chunks of 128 rows; xas staged from gx ----
    int tx4 = tid & 15;
    int tm4 = tid >> 4;
    for (int ch = 0; ch < 4; ch++) {
        int R = ch * 128;
        for (int i = tid; i < 8192; i += 512) {
            int r = i >> 6, c = i & 63;
            xas[r * 68 + c] = (R + r < NNODE) ? gx[(size_t)(R + r) * 64 + c] : 0.f;
        }
        __syncthreads();
        float h[4][4];
        #pragma unroll
        for (int i = 0; i < 4; i++)
            #pragma unroll
            for (int j = 0; j < 4; j++) h[i][j] = 0.f;
        #pragma unroll 4
        for (int d4 = 0; d4 < 16; d4++) {
            float4 xv[4], wv[4];
            #pragma unroll
            for (int i = 0; i < 4; i++) xv[i] = *(const float4*)&xas[(tm4 * 4 + i) * 68 + d4 * 4];
            #pragma unroll
            for (int j = 0; j < 4; j++) wv[j] = *(const float4*)&Ws[(tx4 * 4 + j) * 68 + d4 * 4];
            #pragma unroll
            for (int i = 0; i < 4; i++)
                #pragma unroll
                for (int j = 0; j < 4; j++)
                    h[i][j] += xv[i].x * wv[j].x + xv[i].y * wv[j].y + xv[i].z * wv[j].z + xv[i].w * wv[j].w;
        }
        #pragma unroll
        for (int i = 0; i < 4; i++)
            #pragma unroll
            for (int j = 0; j < 4; j++) h[i][j] = geluf(h[i][j] + b2S[tx4 * 4 + j]);
        __syncthreads();
        #pragma unroll
        for (int i = 0; i < 4; i++)
            *(float4*)&hstage[(tm4 * 4 + i) * 68 + tx4 * 4] = make_float4(h[i][0], h[i][1], h[i][2], h[i][3]);
        __syncthreads();
        {
            int ml = tid >> 2, q = tid & 3;
            float s = 0.f;
            #pragma unroll
            for (int d = 0; d < 16; d++) s += hstage[ml * 68 + q * 16 + d];
            s += __shfl_xor_sync(0xffffffffu, s, 1);
            s += __shfl_xor_sync(0xffffffffu, s, 2);
            float mu = s * (1.0f / 64.0f);
            float s2 = 0.f;
            #pragma unroll
            for (int d = 0; d < 16; d++) { float v = hstage[ml * 68 + q * 16 + d] - mu; s2 += v * v; }
            s2 += __shfl_xor_sync(0xffffffffu, s2, 1);
            s2 += __shfl_xor_sync(0xffffffffu, s2, 2);
            if (q == 0) { muS[ml] = mu; rsS[ml] = rsqrtf(s2 * (1.0f / 64.0f) + 1e-5f); }
        }
        __syncthreads();
        #pragma unroll
        for (int i = 0; i < 4; i++) {
            int ml = tm4 * 4 + i, mg = R + ml;
            if (mg < NNODE) {
                float mu = muS[ml], rs = rsS[ml];
                float4 o;
                o.x = (h[i][0] - mu) * rs * gS[tx4 * 4 + 0] + beS[tx4 * 4 + 0];
                o.y = (h[i][1] - mu) * rs * gS[tx4 * 4 + 1] + beS[tx4 * 4 + 1];
                o.z = (h[i][2] - mu) * rs * gS[tx4 * 4 + 2] + beS[tx4 * 4 + 2];
                o.w = (h[i][3] - mu) * rs * gS[tx4 * 4 + 3] + beS[tx4 * 4 + 3];
                *(float4*)&gx[mg * 64 + tx4 * 4] = o;
            }
        }
        __syncthreads();
    }
}

// ---------------- GRU input GEMMs: merged, split-K partials, FFMA2 row-paired ----------------
__global__ __launch_bounds__(256) void k_xp3(const float* __restrict__ Wih_l,
                                             const float* __restrict__ Wih_m,
                                             const float* __restrict__ Wih_s) {
    __shared__ __align__(16) float XsT[32 * 66];
    __shared__ float Wst[32][193];
    const float* Wih; int T, t0, M, Klen; size_t poff; int nbx, nby;
    if (blockIdx.z == 0)      { Wih = Wih_l; T = 256; t0 = 0;   M = 1024; Klen = 4000; poff = 0;       nbx = 16; nby = 8;  }
    else if (blockIdx.z == 1) { Wih = Wih_m; T = 20;  t0 = 236; M = 80;   Klen = 1280; poff = 1572864; nbx = 2;  nby = 25; }
    else                      { Wih = Wih_s; T = 10;  t0 = 246; M = 40;   Klen = 1280; poff = 1956864; nbx = 1;  nby = 25; }
    if (blockIdx.x >= (unsigned)nbx || blockIdx.y >= (unsigned)nby) return;

    int tid = threadIdx.x;
    int tn = tid & 31, tmg = tid >> 5;
    int r0 = blockIdx.x * 64;
    int kb = blockIdx.y * Klen;
    u64 acc2[4][6];
    #pragma unroll
    for (int p = 0; p < 4; p++)
        #pragma unroll
        for (int j = 0; j < 6; j++) acc2[p][j] = 0ull;

    for (int kc = 0; kc < Klen; kc += 32) {
        __syncthreads();
        for (int i = tid; i < 2048; i += 256) {
            int rl = i >> 5, kk = i & 31;
            int r = r0 + rl;
            float v = 0.f;
            if (r < M) {
                int b = r / T, t = t0 + r % T;
                v = g_x[(size_t)(b * 256 + t) * 32000 + kb + kc + kk];
            }
            XsT[kk * 66 + rl] = v;
        }
        for (int i = tid; i < 6144; i += 256) {
            int g = i >> 5, kk = i & 31;
            Wst[kk][g] = Wih[(size_t)g * 32000 + kb + kc + kk];
        }
        __syncthreads();
        #pragma unroll 4
        for (int kk = 0; kk < 32; kk++) {
            u64 xp2[4];
            #pragma unroll
            for (int p = 0; p < 4; p++)
                xp2[p] = *(const u64*)&XsT[kk * 66 + tmg * 8 + 2 * p];
            #pragma unroll
            for (int j = 0; j < 6; j++) {
                u64 ws = splat2(Wst[kk][tn + 32 * j]);
                #pragma unroll
                for (int p = 0; p < 4; p++) acc2[p][j] = ffma2(xp2[p], ws, acc2[p][j]);
            }
        }
    }
    #pragma unroll
    for (int p = 0; p < 4; p++) {
        int ra = r0 + tmg * 8 + 2 * p;
        #pragma unroll
        for (int j = 0; j < 6; j++) {
            float2 f = unpack2(acc2[p][j]);
            if (ra < M)     g_part[poff + ((size_t)blockIdx.y * M + ra) * G3 + tn + 32 * j]     = f.x;
            if (ra + 1 < M) g_part[poff + ((size_t)blockIdx.y * M + ra + 1) * G3 + tn + 32 * j] = f.y;
        }
    }
}

__global__ void k_xpred3(const float* __restrict__ bih_l, const float* __restrict__ bih_m,
                         const float* __restrict__ bih_s) {
    int idx = blockIdx.x * 256 + threadIdx.x;
    if (idx >= 1144 * G3) return;
    int r = idx / G3, c = idx % G3;
    const float* bih; float* xp; size_t poff; int M, nsplit, rl;
    if (r < 1024)      { bih = bih_l; xp = g_xp_l; poff = 0;       M = 1024; nsplit = 8;  rl = r; }
    else if (r < 1104) { bih = bih_m; xp = g_xp_m; poff = 1572864; M = 80;   nsplit = 25; rl = r - 1024; }
    else               { bih = bih_s; xp = g_xp_s; poff = 1956864; M = 40;   nsplit = 25; rl = r - 1104; }
    float a = bih[c];
    for (int s = 0; s < nsplit; s++) a += g_part[poff + ((size_t)s * M + rl) * G3 + c];
    xp[(size_t)rl * G3 + c] = a;
}

// ---------------- GRU scan: grid 12 = 3 GRUs x 4 batches, 192 threads ----------------
#define GRU_SMEM_BYTES ((192 * 68 + 64 + 192 + 192) * 4)
__global__ __launch_bounds__(192) void k_gru(const float* __restrict__ Whh_s, const float* __restrict__ bhh_s,
                                             const float* __restrict__ Whh_m, const float* __restrict__ bhh_m,
                                             const float* __restrict__ Whh_l, const float* __restrict__ bhh_l) {
    extern __shared__ float smg[];
    float* WhhS = smg;                  // [192][68]
    float* hS   = WhhS + 192 * 68;      // [64]
    float* ghS  = hS + 64;              // [192]
    float* bhhS = ghS + 192;            // [192]
    int tid = threadIdx.x;
    int gru = blockIdx.x >> 2, b = blockIdx.x & 3;
    const float* Whh; const float* bhh; const float* xp; int T;
    if (gru == 0)      { Whh = Whh_s; bhh = bhh_s; xp = g_xp_s; T = 10;  }
    else if (gru == 1) { Whh = Whh_m; bhh = bhh_m; xp = g_xp_m; T = 20;  }
    else               { Whh = Whh_l; bhh = bhh_l; xp = g_xp_l; T = 256; }
    float* hout = g_hfin + gru * 256 + b * 64;
    for (int i = tid; i < 192 * 64; i += 192) WhhS[(i >> 6) * 68 + (i & 63)] = Whh[i];
    bhhS[tid] = bhh[tid];
    if (tid < 64) hS[tid] = 0.f;
    __syncthreads();

    for (int t = 0; t < T; t++) {
        {
            int g = tid;
            const ulonglong2* wr = (const ulonglong2*)&WhhS[g * 68];
            const ulonglong2* hr = (const ulonglong2*)&hS[0];
            u64 a2 = 0ull;
            #pragma unroll
            for (int j = 0; j < 16; j++) {
                ulonglong2 w = wr[j], hh = hr[j];
                a2 = ffma2(hh.x, w.x, a2);
                a2 = ffma2(hh.y, w.y, a2);
            }
            float2 f = unpack2(a2);
            ghS[g] = bhhS[g] + f.x + f.y;
        }
        __syncthreads();
        if (tid < 64) {
            int j = tid;
            const float* xpt = xp + ((size_t)b * T + t) * G3;
            float r = sigf(xpt[j]        + ghS[j]);
            float z = sigf(xpt[64 + j]   + ghS[64 + j]);
            float n = tanhf(xpt[128 + j] + r * ghS[128 + j]);
            hS[j] = (1.f - z) * n + z * hS[j];
        }
        __syncthreads();
    }
    if (tid < 64) hout[tid] = hS[tid];
}

// ---------------- head: concat -> gelu(linear) -> linear ----------------
__global__ __launch_bounds__(512) void k_head(const float* __restrict__ W1, const float* __restrict__ b1,
                                              const float* __restrict__ W2, const float* __restrict__ b2,
                                              float* __restrict__ out) {
    __shared__ float hc[4 * 192];
    __shared__ float h1[4 * 64];
    int tid = threadIdx.x;
    for (int i = tid; i < 768; i += 512) {
        int b = i / G3, k = i % G3;
        hc[i] = g_hfin[(k >> 6) * 256 + b * 64 + (k & 63)];
    }
    __syncthreads();
    if (tid < 256) {
        int b = tid >> 6, e = tid & 63;
        float a = b1[e];
        #pragma unroll 8
        for (int k = 0; k < G3; k++) a += hc[b * G3 + k] * W1[e * G3 + k];
        h1[tid] = geluf(a);
    }
    __syncthreads();
    for (int o = tid; o < 2000; o += 512) {
        int b = o / NNODE, n = o % NNODE;
        float a = b2[n];
        #pragma unroll
        for (int e = 0; e < 64; e++) a += h1[b * 64 + e] * W2[n * 64 + e];
        out[o] = a;
    }
}

extern "C" void kernel_launch(void* const* d_in, const int* in_sizes, int n_in,
                              void* d_out, int out_size) {
    const float* x     = (const float*)d_in[0];
    const float* ip_W  = (const float*)d_in[1];
    const float* ip_b  = (const float*)d_in[2];
    const float* fe    = (const float*)d_in[3];
    const float* te    = (const float*)d_in[4];
    const float* gl_W  = (const float*)d_in[5];
    const float* gl_b  = (const float*)d_in[6];
    const float* gl_g  = (const float*)d_in[7];
    const float* gl_be = (const float*)d_in[8];
    const float* Wih_s = (const float*)d_in[9];
    const float* Whh_s = (const float*)d_in[10];
    const float* bih_s = (const float*)d_in[11];
    const float* bhh_s = (const float*)d_in[12];
    const float* Wih_m = (const float*)d_in[13];
    const float* Whh_m = (const float*)d_in[14];
    const float* bih_m = (const float*)d_in[15];
    const float* bhh_m = (const float*)d_in[16];
    const float* Wih_l = (const float*)d_in[17];
    const float* Whh_l = (const float*)d_in[18];
    const float* bih_l = (const float*)d_in[19];
    const float* bhh_l = (const float*)d_in[20];
    const float* dh_W1 = (const float*)d_in[21];
    const float* dh_b1 = (const float*)d_in[22];
    const float* dh_W2 = (const float*)d_in[23];
    const float* dh_b2 = (const float*)d_in[24];
    float* out = (float*)d_out;

    cudaFuncSetAttribute(k_layer, cudaFuncAttributeMaxDynamicSharedMemorySize, LAYER_SMEM_BYTES);
    cudaFuncSetAttribute(k_gru,   cudaFuncAttributeMaxDynamicSharedMemorySize, GRU_SMEM_BYTES);

    k_adj<<<NNODE, 256>>>(fe, te);
    k_adjsplit<<<512, 256>>>();
    k_iproj<<<8000, 512>>>(x, ip_W, ip_b);

    for (int i = 0; i < 2; i++)
        k_layer<<<NB * NS, 512, LAYER_SMEM_BYTES>>>(gl_W + i * 64 * 64, gl_b + i * 64,
                                                    gl_g + i * 64, gl_be + i * 64);

    k_xp3<<<dim3(16, 25, 3), 256>>>(Wih_l, Wih_m, Wih_s);
    k_xpred3<<<(1144 * G3 + 255) / 256, 256>>>(bih_l, bih_m, bih_s);

    k_gru<<<12, 192, GRU_SMEM_BYTES>>>(Whh_s, bhh_s, Whh_m, bhh_m, Whh_l, bhh_l);
    k_head<<<1, 512>>>(dh_W1, dh_b1, dh_W2, dh_b2, out);
}

// round 17
// speedup vs baseline: 1.1457x; 1.1457x over previous
#include <cuda_runtime.h>
#include <cuda_bf16.h>
#include <math.h>
#include <stdint.h>

#define NB 4
#define NS 256
#define NNODE 500
#define DH 64
#define G3 192

typedef unsigned long long u64;

// ---------------- device scratch (no allocations allowed) ----------------
__device__ float g_x[(size_t)NB * NS * NNODE * DH];   // 131 MB activations, in-place across layers
__device__ float g_adjT[NNODE * NNODE];               // adjT[m][n] = adj[n][m] fp32
__device__ __nv_bfloat16 g_adjT_h[512 * 512];         // bf16 split hi, zero-padded to 512x512
__device__ __nv_bfloat16 g_adjT_l[512 * 512];         // bf16 split lo
__device__ float g_part[2148864];                     // split-K partials: l @0, m @1572864, s @1956864
__device__ float g_xp_l[1024 * G3];
__device__ float g_xp_m[80 * G3];
__device__ float g_xp_s[40 * G3];
__device__ float g_hfin[3 * NB * DH];                 // [s,m,l][b][j]

__device__ __forceinline__ float geluf(float x) { return 0.5f * x * (1.0f + erff(x * 0.7071067811865476f)); }
__device__ __forceinline__ float sigf(float x)  { return 1.0f / (1.0f + expf(-x)); }

// packed fp32x2 helpers (exact fp32 math)
__device__ __forceinline__ u64 splat2(float a) {
    u64 r; asm("mov.b64 %0, {%1, %1};" : "=l"(r) : "f"(a)); return r;
}
__device__ __forceinline__ u64 ffma2(u64 a, u64 b, u64 c) {
    u64 d; asm("fma.rn.f32x2 %0, %1, %2, %3;" : "=l"(d) : "l"(a), "l"(b), "l"(c)); return d;
}
__device__ __forceinline__ float2 unpack2(u64 v) {
    float2 f; asm("mov.b64 {%0, %1}, %2;" : "=f"(f.x), "=f"(f.y) : "l"(v)); return f;
}

// HMMA m16n8k16 bf16, fp32 accum (base-target instruction, runs on tensor pipe)
__device__ __forceinline__ void mma16816(float* c, const uint32_t* a, const uint32_t* b) {
    asm volatile("mma.sync.aligned.m16n8k16.row.col.f32.bf16.bf16.f32 "
        "{%0,%1,%2,%3}, {%4,%5,%6,%7}, {%8,%9}, {%0,%1,%2,%3};"
        : "+f"(c[0]), "+f"(c[1]), "+f"(c[2]), "+f"(c[3])
        : "r"(a[0]), "r"(a[1]), "r"(a[2]), "r"(a[3]), "r"(b[0]), "r"(b[1]));
}

// ---------------- adjacency: logits + row softmax, stored transposed ----------------
__global__ void k_adj(const float* __restrict__ fe, const float* __restrict__ tem) {
    __shared__ float sf[32];
    __shared__ float lg[NNODE];
    __shared__ float wred[8];
    int n = blockIdx.x, tid = threadIdx.x;
    if (tid < 32) sf[tid] = fe[n * 32 + tid];
    __syncthreads();
    for (int m = tid; m < NNODE; m += 256) {
        float a = 0.f;
        #pragma unroll
        for (int k = 0; k < 32; k++) a += sf[k] * tem[m * 32 + k];
        lg[m] = a * 2.0f;   // / TEMP (0.5)
    }
    __syncthreads();
    float mx = -1e30f;
    for (int m = tid; m < NNODE; m += 256) mx = fmaxf(mx, lg[m]);
    for (int o = 16; o; o >>= 1) mx = fmaxf(mx, __shfl_xor_sync(0xffffffffu, mx, o));
    if ((tid & 31) == 0) wred[tid >> 5] = mx;
    __syncthreads();
    mx = wred[0];
    #pragma unroll
    for (int w = 1; w < 8; w++) mx = fmaxf(mx, wred[w]);
    float sum = 0.f;
    for (int m = tid; m < NNODE; m += 256) { float e = expf(lg[m] - mx); lg[m] = e; sum += e; }
    for (int o = 16; o; o >>= 1) sum += __shfl_xor_sync(0xffffffffu, sum, o);
    __syncthreads();
    if ((tid & 31) == 0) wred[tid >> 5] = sum;
    __syncthreads();
    sum = 0.f;
    #pragma unroll
    for (int w = 0; w < 8; w++) sum += wred[w];
    float inv = 1.0f / sum;
    for (int m = tid; m < NNODE; m += 256) g_adjT[m * NNODE + n] = lg[m] * inv;
}

// ---------------- adjT bf16 split, zero-padded 512x512 ----------------
__global__ void k_adjsplit() {
    int m = blockIdx.x;
    for (int k = threadIdx.x; k < 512; k += 256) {
        float v = (m < NNODE && k < NNODE) ? g_adjT[m * NNODE + k] : 0.f;
        __nv_bfloat16 h16 = __float2bfloat16(v);
        __nv_bfloat16 l16 = __float2bfloat16(v - __bfloat162float(h16));
        g_adjT_h[m * 512 + k] = h16;
        g_adjT_l[m * 512 + k] = l16;
    }
}

// ---------------- input projection: 64 rows/block, W loaded once ----------------
__global__ __launch_bounds__(512) void k_iproj(const float* __restrict__ x,
                                               const float* __restrict__ W,
                                               const float* __restrict__ b) {
    __shared__ float sW[64 * 33];
    __shared__ float sb[64];
    __shared__ float sx[64 * 32];
    int tid = threadIdx.x;
    for (int i = tid; i < 2048; i += 512) { int d = i >> 5, k = i & 31; sW[d * 33 + k] = W[i]; }
    if (tid < 64) sb[tid] = b[tid];
    size_t row0 = (size_t)blockIdx.x * 64;
    for (int i = tid; i < 2048; i += 512) sx[i] = x[row0 * 32 + i];
    __syncthreads();
    int r = tid >> 6, d = tid & 63;
    #pragma unroll
    for (int g = 0; g < 8; g++) {
        int rr = g * 8 + r;
        float a = sb[d];
        #pragma unroll
        for (int k = 0; k < 32; k++) a += sx[rr * 32 + k] * sW[d * 33 + k];
        g_x[(row0 + rr) * 64 + d] = geluf(a);
    }
}

// ---------------- fused graph layer: HMMA bf16-split agg (single-pass, interleaved B loads) ----------------
// phase1 smem: xsTh [64][520]bf16 @0 (66560) | xsTl @66560 (66560) -> 133120
// persistent:  Ws @133120 (17408) -> 150528 | params @150528 (1792) -> 152320
// phase2 overlays dead xsT region: xas [128][68] @0 (34816) | hstage [128][68] @36864 (-> 71680)
#define XSTR 520
#define LAYER_SMEM_BYTES 152320
__global__ __launch_bounds__(512) void k_layer(const float* __restrict__ W,
                                               const float* __restrict__ bias2,
                                               const float* __restrict__ gamma,
                                               const float* __restrict__ beta) {
    extern __shared__ __align__(16) char smb[];
    __nv_bfloat16* xsTh = (__nv_bfloat16*)smb;            // [64][520]
    __nv_bfloat16* xsTl = (__nv_bfloat16*)(smb + 66560);  // [64][520]
    float* xas    = (float*)smb;                          // phase2 [128][68]
    float* hstage = (float*)(smb + 36864);                // phase2 [128][68]
    float* Ws     = (float*)(smb + 133120);               // [64][68]
    float* b2S    = (float*)(smb + 150528);
    float* gS  = b2S + 64;
    float* beS = gS + 64;
    float* muS = beS + 64;                                // [128]
    float* rsS = muS + 128;                               // [128]
    int tid = threadIdx.x, wid = tid >> 5, lid = tid & 31;
    float* gx = g_x + (size_t)blockIdx.x * (NNODE * DH);

    // weights / LN params
    for (int i = tid; i < 4096; i += 512) { int e = i >> 6, d = i & 63; Ws[e * 68 + d] = W[i]; }
    if (tid < 64) { b2S[tid] = bias2[tid]; gS[tid] = gamma[tid]; beS[tid] = beta[tid]; }

    // build xs^T bf16 hi/lo: xsT[n][k], k zero-padded beyond NNODE
    for (int idx = tid; idx < 32768; idx += 512) {
        int n = idx & 63, k = idx >> 6;
        float v = (k < NNODE) ? gx[(size_t)k * 64 + n] : 0.f;
        __nv_bfloat16 h16 = __float2bfloat16(v);
        __nv_bfloat16 l16 = __float2bfloat16(v - __bfloat162float(h16));
        xsTh[n * XSTR + k] = h16;
        xsTl[n * XSTR + k] = l16;
    }
    __syncthreads();

    // ---- agg via HMMA: warp w computes rows [w*32, w*32+32) x 64 cols, single K pass ----
    // A loaded once per ks (hi then lo); B fragments loaded 2-regs-at-a-time to cap liveness.
    int gr = lid >> 2;            // 0..7
    int kc = (lid & 3) << 1;      // 0,2,4,6
    int m0 = wid * 32;
    int ra = m0 + gr, rb = m0 + 16 + gr;
    float acc[16][4];             // tile t = mt*8+nt
    #pragma unroll
    for (int t = 0; t < 16; t++)
        #pragma unroll
        for (int q = 0; q < 4; q++) acc[t][q] = 0.f;

    #pragma unroll 1
    for (int ks = 0; ks < 32; ks++) {
        int k0 = ks * 16 + kc;
        uint32_t a0[8], bb[2];
        // A hi fragments (global, L2-resident) — loaded ONCE
        a0[0] = *(const uint32_t*)(g_adjT_h + (size_t)ra * 512 + k0);
        a0[1] = *(const uint32_t*)(g_adjT_h + (size_t)(ra + 8) * 512 + k0);
        a0[2] = *(const uint32_t*)(g_adjT_h + (size_t)ra * 512 + k0 + 8);
        a0[3] = *(const uint32_t*)(g_adjT_h + (size_t)(ra + 8) * 512 + k0 + 8);
        a0[4] = *(const uint32_t*)(g_adjT_h + (size_t)rb * 512 + k0);
        a0[5] = *(const uint32_t*)(g_adjT_h + (size_t)(rb + 8) * 512 + k0);
        a0[6] = *(const uint32_t*)(g_adjT_h + (size_t)rb * 512 + k0 + 8);
        a0[7] = *(const uint32_t*)(g_adjT_h + (size_t)(rb + 8) * 512 + k0 + 8);
        // hi*hi: B hi loaded 2 regs at a time
        #pragma unroll
        for (int nt = 0; nt < 8; nt++) {
            bb[0] = *(const uint32_t*)&xsTh[(nt * 8 + gr) * XSTR + k0];
            bb[1] = *(const uint32_t*)&xsTh[(nt * 8 + gr) * XSTR + k0 + 8];
            mma16816(acc[nt],     &a0[0], bb);
            mma16816(acc[8 + nt], &a0[4], bb);
        }
        // hi*lo: B lo
        #pragma unroll
        for (int nt = 0; nt < 8; nt++) {
            bb[0] = *(const uint32_t*)&xsTl[(nt * 8 + gr) * XSTR + k0];
            bb[1] = *(const uint32_t*)&xsTl[(nt * 8 + gr) * XSTR + k0 + 8];
            mma16816(acc[nt],     &a0[0], bb);
            mma16816(acc[8 + nt], &a0[4], bb);
        }
        // A lo (overwrites a0 — ah dead now)
        a0[0] = *(const uint32_t*)(g_adjT_l + (size_t)ra * 512 + k0);
        a0[1] = *(const uint32_t*)(g_adjT_l + (size_t)(ra + 8) * 512 + k0);
        a0[2] = *(const uint32_t*)(g_adjT_l + (size_t)ra * 512 + k0 + 8);
        a0[3] = *(const uint32_t*)(g_adjT_l + (size_t)(ra + 8) * 512 + k0 + 8);
        a0[4] = *(const uint32_t*)(g_adjT_l + (size_t)rb * 512 + k0);
        a0[5] = *(const uint32_t*)(g_adjT_l + (size_t)(rb + 8) * 512 + k0);
        a0[6] = *(const uint32_t*)(g_adjT_l + (size_t)rb * 512 + k0 + 8);
        a0[7] = *(const uint32_t*)(g_adjT_l + (size_t)(rb + 8) * 512 + k0 + 8);
        // lo*hi: B hi reloaded from smem (cheap, conflict-free)
        #pragma unroll
        for (int nt = 0; nt < 8; nt++) {
            bb[0] = *(const uint32_t*)&xsTh[(nt * 8 + gr) * XSTR + k0];
            bb[1] = *(const uint32_t*)&xsTh[(nt * 8 + gr) * XSTR + k0 + 8];
            mma16816(acc[nt],     &a0[0], bb);
            mma16816(acc[8 + nt], &a0[4], bb);
        }
    }
    // epilogue: xa = x + agg, written back into gx (each warp owns its rows/cols)
    #pragma unroll
    for (int mt = 0; mt < 2; mt++) {
        #pragma unroll
        for (int nt = 0; nt < 8; nt++) {
            float* a4 = acc[mt * 8 + nt];
            int r1 = m0 + mt * 16 + gr;
            int r2 = r1 + 8;
            int c  = nt * 8 + kc;
            if (r1 < NNODE) {
                float2 res = *(const float2*)(gx + (size_t)r1 * 64 + c);
                *(float2*)(gx + (size_t)r1 * 64 + c) = make_float2(res.x + a4[0], res.y + a4[1]);
            }
            if (r2 < NNODE) {
                float2 res = *(const float2*)(gx + (size_t)r2 * 64 + c);
                *(float2*)(gx + (size_t)r2 * 64 + c) = make_float2(res.x + a4[2], res.y + a4[3]);
            }
        }
    }
    __syncthreads();   // all xa writes to gx visible; xsT dead

    // ---- mm2 + gelu + layernorm in 4 chunks of 128 rows; xas staged from gx ----
    int tx4 = tid & 15;
    int tm4 = tid >> 4;
    for (int ch = 0; ch < 4; ch++) {
        int R = ch * 128;
        for (int i = tid; i < 8192; i += 512) {
            int r = i >> 6, c = i & 63;
            xas[r * 68 + c] = (R + r < NNODE) ? gx[(size_t)(R + r) * 64 + c] : 0.f;
        }
        __syncthreads();
        float h[4][4];
        #pragma unroll
        for (int i = 0; i < 4; i++)
            #pragma unroll
            for (int j = 0; j < 4; j++) h[i][j] = 0.f;
        #pragma unroll 4
        for (int d4 = 0; d4 < 16; d4++) {
            float4 xv[4], wv[4];
            #pragma unroll
            for (int i = 0; i < 4; i++) xv[i] = *(const float4*)&xas[(tm4 * 4 + i) * 68 + d4 * 4];
            #pragma unroll
            for (int j = 0; j < 4; j++) wv[j] = *(const float4*)&Ws[(tx4 * 4 + j) * 68 + d4 * 4];
            #pragma unroll
            for (int i = 0; i < 4; i++)
                #pragma unroll
                for (int j = 0; j < 4; j++)
                    h[i][j] += xv[i].x * wv[j].x + xv[i].y * wv[j].y + xv[i].z * wv[j].z + xv[i].w * wv[j].w;
        }
        #pragma unroll
        for (int i = 0; i < 4; i++)
            #pragma unroll
            for (int j = 0; j < 4; j++) h[i][j] = geluf(h[i][j] + b2S[tx4 * 4 + j]);
        __syncthreads();
        #pragma unroll
        for (int i = 0; i < 4; i++)
            *(float4*)&hstage[(tm4 * 4 + i) * 68 + tx4 * 4] = make_float4(h[i][0], h[i][1], h[i][2], h[i][3]);
        __syncthreads();
        {
            int ml = tid >> 2, q = tid & 3;
            float s = 0.f;
            #pragma unroll
            for (int d = 0; d < 16; d++) s += hstage[ml * 68 + q * 16 + d];
            s += __shfl_xor_sync(0xffffffffu, s, 1);
            s += __shfl_xor_sync(0xffffffffu, s, 2);
            float mu = s * (1.0f / 64.0f);
            float s2 = 0.f;
            #pragma unroll
            for (int d = 0; d < 16; d++) { float v = hstage[ml * 68 + q * 16 + d] - mu; s2 += v * v; }
            s2 += __shfl_xor_sync(0xffffffffu, s2, 1);
            s2 += __shfl_xor_sync(0xffffffffu, s2, 2);
            if (q == 0) { muS[ml] = mu; rsS[ml] = rsqrtf(s2 * (1.0f / 64.0f) + 1e-5f); }
        }
        __syncthreads();
        #pragma unroll
        for (int i = 0; i < 4; i++) {
            int ml = tm4 * 4 + i, mg = R + ml;
            if (mg < NNODE) {
                float mu = muS[ml], rs = rsS[ml];
                float4 o;
                o.x = (h[i][0] - mu) * rs * gS[tx4 * 4 + 0] + beS[tx4 * 4 + 0];
                o.y = (h[i][1] - mu) * rs * gS[tx4 * 4 + 1] + beS[tx4 * 4 + 1];
                o.z = (h[i][2] - mu) * rs * gS[tx4 * 4 + 2] + beS[tx4 * 4 + 2];
                o.w = (h[i][3] - mu) * rs * gS[tx4 * 4 + 3] + beS[tx4 * 4 + 3];
                *(float4*)&gx[mg * 64 + tx4 * 4] = o;
            }
        }
        __syncthreads();
    }
}

// ---------------- GRU input GEMMs: merged, split-K partials, FFMA2 row-paired ----------------
__global__ __launch_bounds__(256) void k_xp3(const float* __restrict__ Wih_l,
                                             const float* __restrict__ Wih_m,
                                             const float* __restrict__ Wih_s) {
    __shared__ __align__(16) float XsT[32 * 66];
    __shared__ float Wst[32][193];
    const float* Wih; int T, t0, M, Klen; size_t poff; int nbx, nby;
    if (blockIdx.z == 0)      { Wih = Wih_l; T = 256; t0 = 0;   M = 1024; Klen = 4000; poff = 0;       nbx = 16; nby = 8;  }
    else if (blockIdx.z == 1) { Wih = Wih_m; T = 20;  t0 = 236; M = 80;   Klen = 1280; poff = 1572864; nbx = 2;  nby = 25; }
    else                      { Wih = Wih_s; T = 10;  t0 = 246; M = 40;   Klen = 1280; poff = 1956864; nbx = 1;  nby = 25; }
    if (blockIdx.x >= (unsigned)nbx || blockIdx.y >= (unsigned)nby) return;

    int tid = threadIdx.x;
    int tn = tid & 31, tmg = tid >> 5;
    int r0 = blockIdx.x * 64;
    int kb = blockIdx.y * Klen;
    u64 acc2[4][6];
    #pragma unroll
    for (int p = 0; p < 4; p++)
        #pragma unroll
        for (int j = 0; j < 6; j++) acc2[p][j] = 0ull;

    for (int kc = 0; kc < Klen; kc += 32) {
        __syncthreads();
        for (int i = tid; i < 2048; i += 256) {
            int rl = i >> 5, kk = i & 31;
            int r = r0 + rl;
            float v = 0.f;
            if (r < M) {
                int b = r / T, t = t0 + r % T;
                v = g_x[(size_t)(b * 256 + t) * 32000 + kb + kc + kk];
            }
            XsT[kk * 66 + rl] = v;
        }
        for (int i = tid; i < 6144; i += 256) {
            int g = i >> 5, kk = i & 31;
            Wst[kk][g] = Wih[(size_t)g * 32000 + kb + kc + kk];
        }
        __syncthreads();
        #pragma unroll 4
        for (int kk = 0; kk < 32; kk++) {
            u64 xp2[4];
            #pragma unroll
            for (int p = 0; p < 4; p++)
                xp2[p] = *(const u64*)&XsT[kk * 66 + tmg * 8 + 2 * p];
            #pragma unroll
            for (int j = 0; j < 6; j++) {
                u64 ws = splat2(Wst[kk][tn + 32 * j]);
                #pragma unroll
                for (int p = 0; p < 4; p++) acc2[p][j] = ffma2(xp2[p], ws, acc2[p][j]);
            }
        }
    }
    #pragma unroll
    for (int p = 0; p < 4; p++) {
        int ra = r0 + tmg * 8 + 2 * p;
        #pragma unroll
        for (int j = 0; j < 6; j++) {
            float2 f = unpack2(acc2[p][j]);
            if (ra < M)     g_part[poff + ((size_t)blockIdx.y * M + ra) * G3 + tn + 32 * j]     = f.x;
            if (ra + 1 < M) g_part[poff + ((size_t)blockIdx.y * M + ra + 1) * G3 + tn + 32 * j] = f.y;
        }
    }
}

__global__ void k_xpred3(const float* __restrict__ bih_l, const float* __restrict__ bih_m,
                         const float* __restrict__ bih_s) {
    int idx = blockIdx.x * 256 + threadIdx.x;
    if (idx >= 1144 * G3) return;
    int r = idx / G3, c = idx % G3;
    const float* bih; float* xp; size_t poff; int M, nsplit, rl;
    if (r < 1024)      { bih = bih_l; xp = g_xp_l; poff = 0;       M = 1024; nsplit = 8;  rl = r; }
    else if (r < 1104) { bih = bih_m; xp = g_xp_m; poff = 1572864; M = 80;   nsplit = 25; rl = r - 1024; }
    else               { bih = bih_s; xp = g_xp_s; poff = 1956864; M = 40;   nsplit = 25; rl = r - 1104; }
    float a = bih[c];
    for (int s = 0; s < nsplit; s++) a += g_part[poff + ((size_t)s * M + rl) * G3 + c];
    xp[(size_t)rl * G3 + c] = a;
}

// ---------------- GRU scan: grid 12 = 3 GRUs x 4 batches, 192 threads ----------------
#define GRU_SMEM_BYTES ((192 * 68 + 64 + 192 + 192) * 4)
__global__ __launch_bounds__(192) void k_gru(const float* __restrict__ Whh_s, const float* __restrict__ bhh_s,
                                             const float* __restrict__ Whh_m, const float* __restrict__ bhh_m,
                                             const float* __restrict__ Whh_l, const float* __restrict__ bhh_l) {
    extern __shared__ float smg[];
    float* WhhS = smg;                  // [192][68]
    float* hS   = WhhS + 192 * 68;      // [64]
    float* ghS  = hS + 64;              // [192]
    float* bhhS = ghS + 192;            // [192]
    int tid = threadIdx.x;
    int gru = blockIdx.x >> 2, b = blockIdx.x & 3;
    const float* Whh; const float* bhh; const float* xp; int T;
    if (gru == 0)      { Whh = Whh_s; bhh = bhh_s; xp = g_xp_s; T = 10;  }
    else if (gru == 1) { Whh = Whh_m; bhh = bhh_m; xp = g_xp_m; T = 20;  }
    else               { Whh = Whh_l; bhh = bhh_l; xp = g_xp_l; T = 256; }
    float* hout = g_hfin + gru * 256 + b * 64;
    for (int i = tid; i < 192 * 64; i += 192) WhhS[(i >> 6) * 68 + (i & 63)] = Whh[i];
    bhhS[tid] = bhh[tid];
    if (tid < 64) hS[tid] = 0.f;
    __syncthreads();

    for (int t = 0; t < T; t++) {
        {
            int g = tid;
            const ulonglong2* wr = (const ulonglong2*)&WhhS[g * 68];
            const ulonglong2* hr = (const ulonglong2*)&hS[0];
            u64 a2 = 0ull;
            #pragma unroll
            for (int j = 0; j < 16; j++) {
                ulonglong2 w = wr[j], hh = hr[j];
                a2 = ffma2(hh.x, w.x, a2);
                a2 = ffma2(hh.y, w.y, a2);
            }
            float2 f = unpack2(a2);
            ghS[g] = bhhS[g] + f.x + f.y;
        }
        __syncthreads();
        if (tid < 64) {
            int j = tid;
            const float* xpt = xp + ((size_t)b * T + t) * G3;
            float r = sigf(xpt[j]        + ghS[j]);
            float z = sigf(xpt[64 + j]   + ghS[64 + j]);
            float n = tanhf(xpt[128 + j] + r * ghS[128 + j]);
            hS[j] = (1.f - z) * n + z * hS[j];
        }
        __syncthreads();
    }
    if (tid < 64) hout[tid] = hS[tid];
}

// ---------------- head: concat -> gelu(linear) -> linear ----------------
__global__ __launch_bounds__(512) void k_head(const float* __restrict__ W1, const float* __restrict__ b1,
                                              const float* __restrict__ W2, const float* __restrict__ b2,
                                              float* __restrict__ out) {
    __shared__ float hc[4 * 192];
    __shared__ float h1[4 * 64];
    int tid = threadIdx.x;
    for (int i = tid; i < 768; i += 512) {
        int b = i / G3, k = i % G3;
        hc[i] = g_hfin[(k >> 6) * 256 + b * 64 + (k & 63)];
    }
    __syncthreads();
    if (tid < 256) {
        int b = tid >> 6, e = tid & 63;
        float a = b1[e];
        #pragma unroll 8
        for (int k = 0; k < G3; k++) a += hc[b * G3 + k] * W1[e * G3 + k];
        h1[tid] = geluf(a);
    }
    __syncthreads();
    for (int o = tid; o < 2000; o += 512) {
        int b = o / NNODE, n = o % NNODE;
        float a = b2[n];
        #pragma unroll
        for (int e = 0; e < 64; e++) a += h1[b * 64 + e] * W2[n * 64 + e];
        out[o] = a;
    }
}

extern "C" void kernel_launch(void* const* d_in, const int* in_sizes, int n_in,
                              void* d_out, int out_size) {
    const float* x     = (const float*)d_in[0];
    const float* ip_W  = (const float*)d_in[1];
    const float* ip_b  = (const float*)d_in[2];
    const float* fe    = (const float*)d_in[3];
    const float* te    = (const float*)d_in[4];
    const float* gl_W  = (const float*)d_in[5];
    const float* gl_b  = (const float*)d_in[6];
    const float* gl_g  = (const float*)d_in[7];
    const float* gl_be = (const float*)d_in[8];
    const float* Wih_s = (const float*)d_in[9];
    const float* Whh_s = (const float*)d_in[10];
    const float* bih_s = (const float*)d_in[11];
    const float* bhh_s = (const float*)d_in[12];
    const float* Wih_m = (const float*)d_in[13];
    const float* Whh_m = (const float*)d_in[14];
    const float* bih_m = (const float*)d_in[15];
    const float* bhh_m = (const float*)d_in[16];
    const float* Wih_l = (const float*)d_in[17];
    const float* Whh_l = (const float*)d_in[18];
    const float* bih_l = (const float*)d_in[19];
    const float* bhh_l = (const float*)d_in[20];
    const float* dh_W1 = (const float*)d_in[21];
    const float* dh_b1 = (const float*)d_in[22];
    const float* dh_W2 = (const float*)d_in[23];
    const float* dh_b2 = (const float*)d_in[24];
    float* out = (float*)d_out;

    cudaFuncSetAttribute(k_layer, cudaFuncAttributeMaxDynamicSharedMemorySize, LAYER_SMEM_BYTES);
    cudaFuncSetAttribute(k_gru,   cudaFuncAttributeMaxDynamicSharedMemorySize, GRU_SMEM_BYTES);

    k_adj<<<NNODE, 256>>>(fe, te);
    k_adjsplit<<<512, 256>>>();
    k_iproj<<<8000, 512>>>(x, ip_W, ip_b);

    for (int i = 0; i < 2; i++)
        k_layer<<<NB * NS, 512, LAYER_SMEM_BYTES>>>(gl_W + i * 64 * 64, gl_b + i * 64,
                                                    gl_g + i * 64, gl_be + i * 64);

    k_xp3<<<dim3(16, 25, 3), 256>>>(Wih_l, Wih_m, Wih_s);
    k_xpred3<<<(1144 * G3 + 255) / 256, 256>>>(bih_l, bih_m, bih_s);

    k_gru<<<12, 192, GRU_SMEM_BYTES>>>(Whh_s, bhh_s, Whh_m, bhh_m, Whh_l, bhh_l);
    k_head<<<1, 512>>>(dh_W1, dh_b1, dh_W2, dh_b2, out);
}